// round 10
// baseline (speedup 1.0000x reference)
#include <cuda_runtime.h>

// Sparse CG tensor product:
//   out[b, M[i]] += scale[i] * x[b, M1[i]] * y[b, M2[i]]
//
// Persistent CTAs (grid = 148, 1 CTA/SM): each CTA loops over several 32-row
// batch tiles, prefetching the NEXT tile's x/y into registers while computing
// the current one => DRAM streaming overlaps compute (fixes the fill/compute
// phase serialization that capped previous rounds at ~100us).
//
// Tiles in smem as [32 rows][stride 513]: gather addr = lane*513 + m -> bank
// (lane + m) mod 32, a permutation over lanes => conflict-free. Odd stride =>
// scalar fill/drain, lane -> consecutive d (conflict-free STS/LDS, coalesced
// LDG/STG).
//
// Path metadata packed to 8B {(m2<<20)|(m1<<10)|m, scale}, staged per-warp
// into smem, consumed as broadcast LDS.64 (2 wavefronts/path). M sorted =>
// register accumulation, one smem store per column change; per-warp ranges
// segment-aligned => single writer per output column, no atomics.

#define DIMC    512
#define STRIDE  513
#define TILE    (32 * STRIDE)          // 16416 floats
#define NWARP   32
#define NTHR    (NWARP * 32)           // 1024
#define CHUNK   64
#define MAXNNZ  8192
#define GRID    148

__device__ int2 g_pk[MAXNNZ];          // {(m2<<20)|(m1<<10)|m, bits(scale)}
__device__ int  g_wstart[NWARP + 1];

// ---------------------------------------------------------------------------
__global__ void pack_kernel(const float* __restrict__ scale,
                            const int* __restrict__ M,
                            const int* __restrict__ M1,
                            const int* __restrict__ M2,
                            int nnz)
{
    int i = blockIdx.x * blockDim.x + threadIdx.x;
    if (i < nnz) {
        g_pk[i] = make_int2((M2[i] << 20) | (M1[i] << 10) | M[i],
                            __float_as_int(scale[i]));
    }
    if (i == 0) {
        g_wstart[0] = 0;
        g_wstart[NWARP] = nnz;
        int prev = 0;
        for (int w = 1; w < NWARP; w++) {
            int t = (int)(((long long)w * nnz) / NWARP);
            if (t < prev) t = prev;
            while (t > 0 && t < nnz && M[t] == M[t - 1]) t++;  // segment align
            g_wstart[w] = t;
            prev = t;
        }
    }
}

// ---------------------------------------------------------------------------
__global__ __launch_bounds__(NTHR, 1)
void tp_kernel(const float* __restrict__ x,
               const float* __restrict__ y,
               float* __restrict__ out,
               int Brows, int ntiles)
{
    extern __shared__ float sm[];
    float* xs = sm;                          // [32][STRIDE]
    float* ys = sm + TILE;
    float* os = sm + 2 * TILE;
    int2*  spath = (int2*)(sm + 3 * TILE);   // [NWARP][CHUNK]

    const int tid  = threadIdx.x;
    const int lane = tid & 31;
    const int warp = tid >> 5;

    const int istart = g_wstart[warp];
    const int iend   = g_wstart[warp + 1];

    // zero output tile once; drain re-zeros after each tile
    for (int idx = tid; idx < TILE; idx += NTHR) os[idx] = 0.f;

    const int glimit = Brows * DIMC - 1;
    const int stride_t = gridDim.x;

    // ---- prologue: prefetch first tile into registers ----
    float rx[16], ry[16];
    int t = blockIdx.x;
    if (t < ntiles) {
        const int gbase = t << 14;           // t * 32 * 512
        #pragma unroll
        for (int it = 0; it < 16; it++) {
            int g = min(gbase + it * NTHR + tid, glimit);
            rx[it] = __ldg(x + g);
            ry[it] = __ldg(y + g);
        }
    }

    const int brow = tid >> 9;               // 0 or 1
    const int dcol = tid & 511;

    for (; t < ntiles; t += stride_t) {
        __syncthreads();                      // prev drain done; os zeroed

        // ---- commit prefetched regs into smem tiles (conflict-free STS) ----
        #pragma unroll
        for (int it = 0; it < 16; it++) {
            int s = (2 * it + brow) * STRIDE + dcol;
            xs[s] = rx[it];
            ys[s] = ry[it];
        }
        __syncthreads();

        // ---- issue prefetch for next tile (hidden under compute) ----
        {
            int tn = t + stride_t;
            if (tn < ntiles) {
                const int gbase = tn << 14;
                #pragma unroll
                for (int it = 0; it < 16; it++) {
                    int g = min(gbase + it * NTHR + tid, glimit);
                    rx[it] = __ldg(x + g);
                    ry[it] = __ldg(y + g);
                }
            }
        }

        // ---- per-warp path processing ----
        if (istart < iend) {
            int2* sp = spath + warp * CHUNK;
            const float* xsl = xs + lane * STRIDE;
            const float* ysl = ys + lane * STRIDE;
            float*       osl = os + lane * STRIDE;

            // chunk 0: clamped, scale zeroed past end (clamped entries repeat
            // the last m => no spurious flush; FFMA adds 0).
            int2 r0, r1;
            {
                int i0 = istart + lane;
                r0 = g_pk[min(i0, iend - 1)];
                if (i0 >= iend) r0.y = 0;
                int i1 = i0 + 32;
                r1 = g_pk[min(i1, iend - 1)];
                if (i1 >= iend) r1.y = 0;
            }

            float acc  = 0.f;
            int   mcur = __shfl_sync(0xffffffffu, r0.x, 0) & 511;

            for (int base = istart; base < iend; base += CHUNK) {
                sp[lane]      = r0;
                sp[lane + 32] = r1;
                __syncwarp();

                // prefetch next metadata chunk (overlaps processing)
                {
                    int i0 = base + CHUNK + lane;
                    r0 = g_pk[min(i0, iend - 1)];
                    if (i0 >= iend) r0.y = 0;
                    int i1 = i0 + 32;
                    r1 = g_pk[min(i1, iend - 1)];
                    if (i1 >= iend) r1.y = 0;
                }

                #pragma unroll 4
                for (int j = 0; j < CHUNK; j++) {
                    int2 p = sp[j];                 // broadcast LDS.64 (2 wf)
                    int m  = p.x & 511;
                    int m1 = (p.x >> 10) & 511;
                    int m2 = (int)((unsigned)p.x >> 20);
                    if (m != mcur) {                // warp-uniform
                        osl[mcur] = acc;            // single owner, no atomic
                        acc  = 0.f;
                        mcur = m;
                    }
                    acc = fmaf(__int_as_float(p.y) * xsl[m1], ysl[m2], acc);
                }
                __syncwarp();
            }
            osl[mcur] = acc;                        // final flush
        }
        __syncthreads();

        // ---- drain output tile + re-zero (scalar LDS/STS, coalesced STG) ----
        {
            const int b0 = t << 5;
            const int nb = min(32, Brows - b0);
            const int gbase = t << 14;
            if (nb == 32) {
                #pragma unroll 4
                for (int it = 0; it < 16; it++) {
                    int idx = it * NTHR + tid;
                    int b = idx >> 9;
                    int d = idx & 511;
                    int s = b * STRIDE + d;
                    out[gbase + idx] = os[s];
                    os[s] = 0.f;
                }
            } else {
                for (int idx = tid; idx < 32 * DIMC; idx += NTHR) {
                    int b = idx >> 9;
                    int d = idx & 511;
                    int s = b * STRIDE + d;
                    if (b < nb) out[(b0 + b) * DIMC + d] = os[s];
                    os[s] = 0.f;
                }
            }
        }
    }
}

// ---------------------------------------------------------------------------
extern "C" void kernel_launch(void* const* d_in, const int* in_sizes, int n_in,
                              void* d_out, int out_size)
{
    const float* x     = (const float*)d_in[0];
    const float* y     = (const float*)d_in[1];
    const float* scale = (const float*)d_in[2];
    const int*   M     = (const int*)d_in[3];
    const int*   M1    = (const int*)d_in[4];
    const int*   M2    = (const int*)d_in[5];
    float*       out   = (float*)d_out;

    const int B      = in_sizes[0] / DIMC;
    const int nnz    = in_sizes[2];
    const int ntiles = (B + 31) / 32;

    const size_t smem_bytes = (size_t)3 * TILE * sizeof(float)
                            + (size_t)NWARP * CHUNK * sizeof(int2); // 213376 B
    cudaFuncSetAttribute(tp_kernel, cudaFuncAttributeMaxDynamicSharedMemorySize,
                         (int)smem_bytes);

    pack_kernel<<<(nnz + 255) / 256, 256>>>(scale, M, M1, M2, nnz);

    const int nblocks = (ntiles < GRID) ? ntiles : GRID;
    tp_kernel<<<nblocks, NTHR, smem_bytes>>>(x, y, out, B, ntiles);
}

// round 11
// speedup vs baseline: 1.1448x; 1.1448x over previous
#include <cuda_runtime.h>

// Sparse CG tensor product:
//   out[b, M[i]] += scale[i] * x[b, M1[i]] * y[b, M2[i]]
//
// Single persistent kernel (one graph node). One CTA = 32 batch rows/tile,
// 32 warps; CTA loops over tiles with register prefetch of the next tile's
// x/y (DRAM streams under compute).
//
// Tiles in smem as [32 rows][stride 513]: gather addr = lane*513 + m ->
// bank (lane + m) mod 32, a permutation over lanes => conflict-free.
// Odd stride => scalar fill/drain, lane -> consecutive d (conflict-free
// STS/LDS, coalesced LDG/STG).
//
// Path metadata staged per warp per 32-path chunk directly from the input
// arrays as int4 {m<<2, m1<<2, m2<<2, scale} (pre-scaled byte offsets =>
// ZERO unpack/scaling instructions in the hot loop); consumed as broadcast
// LDS.128 (same address across lanes => conflict-degree 1). M sorted =>
// register accumulation, one smem store per column change; per-warp ranges
// segment-aligned (computed locally, monotone scan) => single writer per
// output column, no atomics.

#define DIMC    512
#define STRIDE  513
#define TILE    (32 * STRIDE)          // 16416 floats
#define NWARP   32
#define NTHR    (NWARP * 32)           // 1024
#define CHUNK   32
#define GRID    148

__global__ __launch_bounds__(NTHR, 1)
void tp_kernel(const float* __restrict__ x,
               const float* __restrict__ y,
               const float* __restrict__ scale,
               const int*   __restrict__ M,
               const int*   __restrict__ M1,
               const int*   __restrict__ M2,
               float* __restrict__ out,
               int Brows, int ntiles, int nnz)
{
    extern __shared__ float sm[];
    float* xs = sm;                          // [32][STRIDE]
    float* ys = sm + TILE;
    float* os = sm + 2 * TILE;
    int4*  spath = (int4*)(sm + 3 * TILE);   // [NWARP][CHUNK]

    const int tid  = threadIdx.x;
    const int lane = tid & 31;
    const int warp = tid >> 5;

    // ---- per-warp segment-aligned path range (local, no setup kernel) ----
    // advance-to-boundary is monotone in the start point => ranges are
    // consistent across warps; a segment spanning a raw boundary yields an
    // empty range for the middle warp(s).
    int istart = (int)(((long long)warp * nnz) / NWARP);
    while (istart > 0 && istart < nnz && M[istart] == M[istart - 1]) istart++;
    int iend = (int)(((long long)(warp + 1) * nnz) / NWARP);
    while (iend > 0 && iend < nnz && M[iend] == M[iend - 1]) iend++;
    if (warp == NWARP - 1) iend = nnz;

    // zero output tile once; drain re-zeros after each tile
    for (int idx = tid; idx < TILE; idx += NTHR) os[idx] = 0.f;

    const bool exact = (Brows == ntiles * 32);   // 20000 = 625*32: true
    const int  stride_t = gridDim.x;

    // ---- prologue: prefetch first tile into registers ----
    float rx[16], ry[16];
    int t = blockIdx.x;
    if (t < ntiles && exact) {
        const int gbase = t << 14;               // t * 32 * 512
        #pragma unroll
        for (int it = 0; it < 16; it++) {
            rx[it] = __ldg(x + gbase + it * NTHR + tid);
            ry[it] = __ldg(y + gbase + it * NTHR + tid);
        }
    }

    const int brow = tid >> 9;                   // 0 or 1
    const int dcol = tid & 511;

    for (; t < ntiles; t += stride_t) {
        __syncthreads();                          // prev drain done; os zeroed

        // ---- commit prefetched regs into smem tiles (conflict-free STS) ----
        if (exact) {
            #pragma unroll
            for (int it = 0; it < 16; it++) {
                int s = (2 * it + brow) * STRIDE + dcol;
                xs[s] = rx[it];
                ys[s] = ry[it];
            }
        } else {
            const int b0 = t << 5;
            for (int idx = tid; idx < 32 * DIMC; idx += NTHR) {
                int b = idx >> 9;
                int d = idx & 511;
                float vx = 0.f, vy = 0.f;
                if (b0 + b < Brows) {
                    vx = x[(b0 + b) * DIMC + d];
                    vy = y[(b0 + b) * DIMC + d];
                }
                int s = b * STRIDE + d;
                xs[s] = vx;
                ys[s] = vy;
            }
        }
        __syncthreads();

        // ---- issue prefetch for next tile (hidden under compute) ----
        {
            int tn = t + stride_t;
            if (tn < ntiles && exact) {
                const int gbase = tn << 14;
                #pragma unroll
                for (int it = 0; it < 16; it++) {
                    rx[it] = __ldg(x + gbase + it * NTHR + tid);
                    ry[it] = __ldg(y + gbase + it * NTHR + tid);
                }
            }
        }

        // ---- per-warp path processing ----
        if (istart < iend) {
            int4* sp = spath + warp * CHUNK;
            const char* xc = (const char*)(xs + lane * STRIDE);
            const char* yc = (const char*)(ys + lane * STRIDE);
            char*       oc = (char*)(os + lane * STRIDE);

            // stage chunk 0 into registers (4 coalesced LDG.32, L1-hot)
            int4 v;
            {
                int i0 = istart + lane;
                int ic = min(i0, iend - 1);
                v.x = M[ic] << 2;
                v.y = M1[ic] << 2;
                v.z = M2[ic] << 2;
                float s = (i0 < iend) ? scale[ic] : 0.f;  // clamped => no
                v.w = __float_as_int(s);                  // spurious flush
            }

            float acc  = 0.f;
            int   mcur = __shfl_sync(0xffffffffu, v.x, 0);  // first M<<2

            for (int base = istart; base < iend; base += CHUNK) {
                sp[lane] = v;
                __syncwarp();

                // stage next chunk (overlaps processing)
                {
                    int i0 = base + CHUNK + lane;
                    int ic = min(i0, iend - 1);
                    v.x = M[ic] << 2;
                    v.y = M1[ic] << 2;
                    v.z = M2[ic] << 2;
                    float s = (i0 < iend) ? scale[ic] : 0.f;
                    v.w = __float_as_int(s);
                }

                #pragma unroll 8
                for (int j = 0; j < CHUNK; j++) {
                    int4 p = sp[j];              // broadcast LDS.128 (N=1)
                    if (p.x != mcur) {           // warp-uniform
                        *(float*)(oc + mcur) = acc;   // single owner
                        acc  = 0.f;
                        mcur = p.x;
                    }
                    acc = fmaf(__int_as_float(p.w) * *(const float*)(xc + p.y),
                               *(const float*)(yc + p.z), acc);
                }
                __syncwarp();
            }
            *(float*)(oc + mcur) = acc;          // final flush
        }
        __syncthreads();

        // ---- drain output tile + re-zero (scalar LDS/STS, coalesced STG) ----
        if (exact) {
            const int gbase = t << 14;
            #pragma unroll 4
            for (int it = 0; it < 16; it++) {
                int idx = it * NTHR + tid;
                int s = (idx >> 9) * STRIDE + (idx & 511);
                out[gbase + idx] = os[s];
                os[s] = 0.f;
            }
        } else {
            const int b0 = t << 5;
            for (int idx = tid; idx < 32 * DIMC; idx += NTHR) {
                int b = idx >> 9;
                int d = idx & 511;
                int s = b * STRIDE + d;
                if (b0 + b < Brows) out[(b0 + b) * DIMC + d] = os[s];
                os[s] = 0.f;
            }
        }
    }
}

// ---------------------------------------------------------------------------
extern "C" void kernel_launch(void* const* d_in, const int* in_sizes, int n_in,
                              void* d_out, int out_size)
{
    const float* x     = (const float*)d_in[0];
    const float* y     = (const float*)d_in[1];
    const float* scale = (const float*)d_in[2];
    const int*   M     = (const int*)d_in[3];
    const int*   M1    = (const int*)d_in[4];
    const int*   M2    = (const int*)d_in[5];
    float*       out   = (float*)d_out;

    const int B      = in_sizes[0] / DIMC;
    const int nnz    = in_sizes[2];
    const int ntiles = (B + 31) / 32;

    const size_t smem_bytes = (size_t)3 * TILE * sizeof(float)
                            + (size_t)NWARP * CHUNK * sizeof(int4); // 213376 B
    cudaFuncSetAttribute(tp_kernel, cudaFuncAttributeMaxDynamicSharedMemorySize,
                         (int)smem_bytes);

    const int nblocks = (ntiles < GRID) ? ntiles : GRID;
    tp_kernel<<<nblocks, NTHR, smem_bytes>>>(x, y, scale, M, M1, M2, out,
                                             B, ntiles, nnz);
}

// round 12
// speedup vs baseline: 1.3110x; 1.1451x over previous
#include <cuda_runtime.h>

// Sparse CG tensor product:
//   out[b, M[i]] += scale[i] * x[b, M1[i]] * y[b, M2[i]]
//
// Single persistent kernel. One CTA = 32 batch rows/tile, 32 warps; CTA loops
// over tiles. Tiles in smem as [32 rows][stride 513]: gather addr =
// lane*513 + m -> bank (lane + m) mod 32, a permutation => conflict-free.
// Odd stride => scalar fill/drain (conflict-free STS/LDS, coalesced LDG/STG).
//
// Crossbar model (validated R8/R11): broadcast LDS costs lanes*width bytes at
// 128B/cyc. So meta is packed to 8B/path: {(M<<22)|(M1<<13)|(M2<<2), scale},
// held in REGISTERS (packed once per kernel), published per 32-path chunk via
// one STS.64 and consumed as broadcast LDS.64 => 2 crossbar cyc/path instead
// of 4 (R11's LDS.128). Unpack is 3 logic ops, no IMAD.
// Hot loop/path: LDS.64 + SHR + SHF/LOP3 + LOP3 + 2x(IADD+LDS.32) + FMUL +
// FFMA + uniform branch => ~4 crossbar cyc/path total.
//
// M sorted => register accumulation, one smem store per column change;
// per-warp ranges segment-aligned => single writer per column, no atomics.

#define DIMC    512
#define STRIDE  513
#define TILE    (32 * STRIDE)          // 16416 floats
#define NWARP   32
#define NTHR    (NWARP * 32)           // 1024
#define MAXC    8                      // meta chunks held in registers
#define GRID    148

__global__ __launch_bounds__(NTHR, 1)
void tp_kernel(const float* __restrict__ x,
               const float* __restrict__ y,
               const float* __restrict__ scale,
               const int*   __restrict__ M,
               const int*   __restrict__ M1,
               const int*   __restrict__ M2,
               float* __restrict__ out,
               int Brows, int ntiles, int nnz)
{
    extern __shared__ float sm[];
    float* xs = sm;                          // [32][STRIDE]
    float* ys = sm + TILE;
    float* os = sm + 2 * TILE;
    int2*  spath = (int2*)(sm + 3 * TILE);   // [NWARP][32]

    const int tid  = threadIdx.x;
    const int lane = tid & 31;
    const int warp = tid >> 5;

    // ---- per-warp segment-aligned path range (lane 0 scans, broadcast) ----
    int istart = 0, iend = 0;
    if (lane == 0) {
        istart = (int)(((long long)warp * nnz) / NWARP);
        while (istart > 0 && istart < nnz && M[istart] == M[istart - 1]) istart++;
        iend = (int)(((long long)(warp + 1) * nnz) / NWARP);
        while (iend > 0 && iend < nnz && M[iend] == M[iend - 1]) iend++;
        if (warp == NWARP - 1) iend = nnz;
    }
    istart = __shfl_sync(0xffffffffu, istart, 0);
    iend   = __shfl_sync(0xffffffffu, iend,   0);
    const int npaths  = iend - istart;
    const int nchunks = (npaths + 31) >> 5;

    // ---- pack this warp's metadata into registers (ONCE per kernel) ----
    // clamped entries repeat the last path's m (no spurious flush), scale=0.
    int2 meta[MAXC];
    #pragma unroll
    for (int c = 0; c < MAXC; c++) {
        meta[c] = make_int2(0, 0);
        if ((c << 5) < npaths) {
            int i0 = istart + (c << 5) + lane;
            int ic = min(i0, iend - 1);
            unsigned w = ((unsigned)M[ic] << 22) | ((unsigned)M1[ic] << 13)
                       | ((unsigned)M2[ic] << 2);
            float s = (i0 < iend) ? scale[ic] : 0.f;
            meta[c] = make_int2((int)w, __float_as_int(s));
        }
    }

    // zero output tile once; drain re-zeros after each tile
    for (int idx = tid; idx < TILE; idx += NTHR) os[idx] = 0.f;

    const bool exact = (Brows == ntiles * 32);   // 20000 = 625*32: true

    for (int t = blockIdx.x; t < ntiles; t += gridDim.x) {
        __syncthreads();                          // prev drain done; os zeroed

        // ---- fill tiles (scalar, conflict-free STS, coalesced LDG) ----
        if (exact) {
            const int gbase = t << 14;            // t * 32 * 512
            #pragma unroll 4
            for (int it = 0; it < 16; it++) {
                int idx = it * NTHR + tid;
                int s = (idx >> 9) * STRIDE + (idx & 511);
                xs[s] = __ldg(x + gbase + idx);
                ys[s] = __ldg(y + gbase + idx);
            }
        } else {
            const int b0 = t << 5;
            for (int idx = tid; idx < 32 * DIMC; idx += NTHR) {
                int b = idx >> 9;
                int d = idx & 511;
                float vx = 0.f, vy = 0.f;
                if (b0 + b < Brows) {
                    vx = x[(b0 + b) * DIMC + d];
                    vy = y[(b0 + b) * DIMC + d];
                }
                int s = b * STRIDE + d;
                xs[s] = vx;
                ys[s] = vy;
            }
        }
        __syncthreads();

        // ---- per-warp path processing ----
        if (npaths > 0) {
            int2* sp = spath + (warp << 5);
            const char* xc = (const char*)(xs + lane * STRIDE);
            const char* yc = (const char*)(ys + lane * STRIDE);
            char*       oc = (char*)(os + lane * STRIDE);

            float acc  = 0.f;
            int   mcur = (int)((unsigned)__shfl_sync(0xffffffffu, meta[0].x, 0)
                               >> 22);

            #define DOCHUNK(MV)                                               \
                do {                                                          \
                    sp[lane] = (MV);                                          \
                    __syncwarp();                                             \
                    _Pragma("unroll")                                         \
                    for (int j = 0; j < 32; j++) {                            \
                        int2 p = sp[j];           /* broadcast LDS.64: 2cyc */\
                        unsigned w = (unsigned)p.x;                           \
                        int mnew = (int)(w >> 22);                            \
                        if (mnew != mcur) {       /* warp-uniform */          \
                            *(float*)(oc + (mcur << 2)) = acc;                \
                            acc  = 0.f;                                       \
                            mcur = mnew;                                      \
                        }                                                     \
                        acc = fmaf(__int_as_float(p.y)                        \
                                     * *(const float*)(xc + ((w >> 11) & 0x7FCu)), \
                                   *(const float*)(yc + (w & 0x7FCu)), acc);  \
                    }                                                         \
                    __syncwarp();                                             \
                } while (0)

            #pragma unroll
            for (int c = 0; c < MAXC; c++) {
                if (c < nchunks) DOCHUNK(meta[c]);
            }
            // overflow chunks (only if a warp owns > MAXC*32 paths)
            for (int c = MAXC; c < nchunks; c++) {
                int i0 = istart + (c << 5) + lane;
                int ic = min(i0, iend - 1);
                unsigned w = ((unsigned)M[ic] << 22) | ((unsigned)M1[ic] << 13)
                           | ((unsigned)M2[ic] << 2);
                float s = (i0 < iend) ? scale[ic] : 0.f;
                int2 v = make_int2((int)w, __float_as_int(s));
                DOCHUNK(v);
            }
            #undef DOCHUNK

            *(float*)(oc + (mcur << 2)) = acc;     // final flush
        }
        __syncthreads();

        // ---- drain output tile + re-zero (scalar, coalesced STG) ----
        if (exact) {
            const int gbase = t << 14;
            #pragma unroll 4
            for (int it = 0; it < 16; it++) {
                int idx = it * NTHR + tid;
                int s = (idx >> 9) * STRIDE + (idx & 511);
                out[gbase + idx] = os[s];
                os[s] = 0.f;
            }
        } else {
            const int b0 = t << 5;
            for (int idx = tid; idx < 32 * DIMC; idx += NTHR) {
                int b = idx >> 9;
                int d = idx & 511;
                int s = b * STRIDE + d;
                if (b0 + b < Brows) out[(b0 + b) * DIMC + d] = os[s];
                os[s] = 0.f;
            }
        }
    }
}

// ---------------------------------------------------------------------------
extern "C" void kernel_launch(void* const* d_in, const int* in_sizes, int n_in,
                              void* d_out, int out_size)
{
    const float* x     = (const float*)d_in[0];
    const float* y     = (const float*)d_in[1];
    const float* scale = (const float*)d_in[2];
    const int*   M     = (const int*)d_in[3];
    const int*   M1    = (const int*)d_in[4];
    const int*   M2    = (const int*)d_in[5];
    float*       out   = (float*)d_out;

    const int B      = in_sizes[0] / DIMC;
    const int nnz    = in_sizes[2];
    const int ntiles = (B + 31) / 32;

    const size_t smem_bytes = (size_t)3 * TILE * sizeof(float)
                            + (size_t)NWARP * 32 * sizeof(int2); // 205184 B
    cudaFuncSetAttribute(tp_kernel, cudaFuncAttributeMaxDynamicSharedMemorySize,
                         (int)smem_bytes);

    const int nblocks = (ntiles < GRID) ? ntiles : GRID;
    tp_kernel<<<nblocks, NTHR, smem_bytes>>>(x, y, scale, M, M1, M2, out,
                                             B, ntiles, nnz);
}